// round 3
// baseline (speedup 1.0000x reference)
#include <cuda_runtime.h>
#include <math.h>
#include <math_constants.h>

#define BSZ      16
#define SEQ      12
#define NODES    512
#define DM       256
#define NH       8
#define DH       32
#define NL       2
#define KK       16
#define DFF      1024
#define NT       (BSZ * NODES)        // 8192 decoder tokens / sequences
#define ET       (NT * KK)            // 131072 encoder tokens
#define DD       (DM * DM)            // 65536

// ------------------------- scratch (device globals; no cudaMalloc allowed) ---
__device__ float g_src[ET * DM];
__device__ float g_y  [ET * DM];
__device__ float g_q  [ET * DM];
__device__ float g_k  [ET * DM];
__device__ float g_v  [ET * DM];
__device__ float g_ao [ET * DM];
__device__ float g_h  [ET * DFF];
__device__ float g_mem[ET * DM];
__device__ float g_tgt[NT * DM];
__device__ float g_ty [NT * DM];
__device__ float g_tq [NT * DM];
__device__ float g_to [NT * DM];
__device__ float g_th [NT * DFF];
__device__ float g_wc [DM * DM];
__device__ int   g_idx[NODES * KK];

// ------------------------------------------------------------------ top-K ----
// index = argsort(-A)[:, :16]  (stable: smaller index wins ties)
__global__ void topk_kernel(const float* __restrict__ A, int* __restrict__ idx) {
    int n = blockIdx.x;
    __shared__ float sv[512];
    __shared__ float rv[256];
    __shared__ int   ri[256];
    int t = threadIdx.x;
    sv[t]       = A[n * 512 + t];
    sv[t + 256] = A[n * 512 + t + 256];
    __syncthreads();
    for (int it = 0; it < KK; it++) {
        float best = sv[t]; int bi = t;
        float v2 = sv[t + 256];
        if (v2 > best) { best = v2; bi = t + 256; }
        rv[t] = best; ri[t] = bi;
        __syncthreads();
        for (int s = 128; s > 0; s >>= 1) {
            if (t < s) {
                if (rv[t + s] > rv[t] || (rv[t + s] == rv[t] && ri[t + s] < ri[t])) {
                    rv[t] = rv[t + s]; ri[t] = ri[t + s];
                }
            }
            __syncthreads();
        }
        if (t == 0) { idx[n * KK + it] = ri[0]; sv[ri[0]] = -CUDART_INF_F; }
        __syncthreads();
    }
}

// ------------------------------------------------------ positional encoding --
__device__ __forceinline__ float pe_val(int p, int d) {
    int i2 = d & ~1;  // 2*i
    float div = expf(-(float)i2 * (9.210340371976184f / 256.f));  // ln(10000)
    float ang = (float)p * div;
    return (d & 1) ? cosf(ang) : sinf(ang);
}

// -------------------------------------------------------------- embeddings ---
// src[(seq*16+j), d] = 16 * sum_s x_c[b,s,idx[n,j]] * Wsrc[s,d] + pe(j,d)
__global__ void embed_src_kernel(const float* __restrict__ xc,
                                 const int* __restrict__ idx,
                                 const float* __restrict__ Wsrc,
                                 float* __restrict__ src) {
    int seq = blockIdx.x;
    int b = seq >> 9, n = seq & 511;
    __shared__ float Ws[SEQ * DM];
    __shared__ float xv[KK * SEQ];
    int t = threadIdx.x;
    for (int i = t; i < SEQ * DM; i += 256) Ws[i] = Wsrc[i];
    if (t < KK * SEQ) {
        int j = t / SEQ, s = t % SEQ;
        int node = idx[n * KK + j];
        xv[t] = xc[(b * SEQ + s) * NODES + node];
    }
    __syncthreads();
    for (int j = 0; j < KK; j++) {
        float acc = 0.f;
        #pragma unroll
        for (int s = 0; s < SEQ; s++) acc += xv[j * SEQ + s] * Ws[s * DM + t];
        src[(seq * KK + j) * DM + t] = acc * 16.f + pe_val(j, t);
    }
}

// tgt[seq, d] = 16 * sum_s x_c[b,s,n] * Wtgt[s,d] + pe(0,d)
__global__ void embed_tgt_kernel(const float* __restrict__ xc,
                                 const float* __restrict__ Wtgt,
                                 float* __restrict__ tgt) {
    int seq = blockIdx.x;
    int b = seq >> 9, n = seq & 511;
    __shared__ float xv[SEQ];
    int t = threadIdx.x;
    if (t < SEQ) xv[t] = xc[(b * SEQ + t) * NODES + n];
    __syncthreads();
    float acc = 0.f;
    #pragma unroll
    for (int s = 0; s < SEQ; s++) acc += xv[s] * Wtgt[s * DM + t];
    tgt[seq * DM + t] = acc * 16.f + ((t & 1) ? 1.f : 0.f);  // pe(0,·)
}

// -------------------------------------------------------------- layernorm ----
// one warp per row of 256
__global__ void ln_kernel(const float* __restrict__ X, float* __restrict__ Y, int rows) {
    int row = blockIdx.x * 8 + (threadIdx.x >> 5);
    if (row >= rows) return;
    int lane = threadIdx.x & 31;
    const float* x = X + (long)row * DM;
    float vals[8];
    float s = 0.f;
    #pragma unroll
    for (int i = 0; i < 8; i++) { vals[i] = x[lane + i * 32]; s += vals[i]; }
    #pragma unroll
    for (int o = 16; o > 0; o >>= 1) s += __shfl_xor_sync(0xffffffffu, s, o);
    float mean = s * (1.f / 256.f);
    float s2 = 0.f;
    #pragma unroll
    for (int i = 0; i < 8; i++) { float d = vals[i] - mean; s2 += d * d; }
    #pragma unroll
    for (int o = 16; o > 0; o >>= 1) s2 += __shfl_xor_sync(0xffffffffu, s2, o);
    float r = rsqrtf(s2 * (1.f / 256.f) + 1e-6f);
    float* y = Y + (long)row * DM;
    #pragma unroll
    for (int i = 0; i < 8; i++) y[lane + i * 32] = (vals[i] - mean) * r;
}

// ------------------------------------------------------------------- GEMM ----
// C[M,N] (op)= A[M,K] @ B[K,N].  M%128==0, N%128==0, K%8==0.
// blockIdx.z selects among NB batched problems sharing A (or not):
//   A_eff = A + z*strideA, B_eff = B + z*strideB, C_eff = C + z*strideC
// EPI: 0 = store, 1 = C += , 2 = relu(store)
template<int EPI>
__global__ void __launch_bounds__(256) sgemm(const float* __restrict__ A,
                                             const float* __restrict__ B,
                                             float* __restrict__ C,
                                             int M, int N, int K,
                                             long strideA, long strideB, long strideC) {
    const int bm = blockIdx.y, bn = blockIdx.x, bz = blockIdx.z;
    A += (long)bz * strideA;
    B += (long)bz * strideB;
    C += (long)bz * strideC;
    __shared__ float As[2][8][128];
    __shared__ float Bs[2][8][128];
    int t = threadIdx.x;
    int tx = t & 15, ty = t >> 4;
    int arow = t >> 1;
    int acol = (t & 1) * 4;
    int brow = t >> 5;
    int bcol = (t & 31) * 4;
    const float* Ag = A + (bm * 128 + arow) * K + acol;
    const float* Bg = B + brow * N + bn * 128 + bcol;

    float acc[8][8];
    #pragma unroll
    for (int i = 0; i < 8; i++)
        #pragma unroll
        for (int j = 0; j < 8; j++) acc[i][j] = 0.f;

    float4 a4 = *(const float4*)Ag;
    float4 b4 = *(const float4*)Bg;
    As[0][acol + 0][arow] = a4.x; As[0][acol + 1][arow] = a4.y;
    As[0][acol + 2][arow] = a4.z; As[0][acol + 3][arow] = a4.w;
    *(float4*)&Bs[0][brow][bcol] = b4;
    __syncthreads();

    int nk = K >> 3;
    for (int kt = 0; kt < nk; kt++) {
        int cur = kt & 1;
        if (kt + 1 < nk) {
            a4 = *(const float4*)(Ag + (kt + 1) * 8);
            b4 = *(const float4*)(Bg + (kt + 1) * 8 * N);
        }
        #pragma unroll
        for (int kk = 0; kk < 8; kk++) {
            float ar[8], br[8];
            *(float4*)(ar)     = *(const float4*)&As[cur][kk][ty * 8];
            *(float4*)(ar + 4) = *(const float4*)&As[cur][kk][ty * 8 + 4];
            *(float4*)(br)     = *(const float4*)&Bs[cur][kk][tx * 8];
            *(float4*)(br + 4) = *(const float4*)&Bs[cur][kk][tx * 8 + 4];
            #pragma unroll
            for (int i = 0; i < 8; i++)
                #pragma unroll
                for (int j = 0; j < 8; j++) acc[i][j] += ar[i] * br[j];
        }
        if (kt + 1 < nk) {
            int nxt = cur ^ 1;
            As[nxt][acol + 0][arow] = a4.x; As[nxt][acol + 1][arow] = a4.y;
            As[nxt][acol + 2][arow] = a4.z; As[nxt][acol + 3][arow] = a4.w;
            *(float4*)&Bs[nxt][brow][bcol] = b4;
            __syncthreads();
        }
    }

    #pragma unroll
    for (int i = 0; i < 8; i++) {
        float* Cp = C + (bm * 128 + ty * 8 + i) * N + bn * 128 + tx * 8;
        float4 r0 = make_float4(acc[i][0], acc[i][1], acc[i][2], acc[i][3]);
        float4 r1 = make_float4(acc[i][4], acc[i][5], acc[i][6], acc[i][7]);
        if (EPI == 1) {
            float4 c0 = *(const float4*)Cp;
            float4 c1 = *((const float4*)Cp + 1);
            r0.x += c0.x; r0.y += c0.y; r0.z += c0.z; r0.w += c0.w;
            r1.x += c1.x; r1.y += c1.y; r1.z += c1.z; r1.w += c1.w;
        }
        if (EPI == 2) {
            r0.x = fmaxf(r0.x, 0.f); r0.y = fmaxf(r0.y, 0.f);
            r0.z = fmaxf(r0.z, 0.f); r0.w = fmaxf(r0.w, 0.f);
            r1.x = fmaxf(r1.x, 0.f); r1.y = fmaxf(r1.y, 0.f);
            r1.z = fmaxf(r1.z, 0.f); r1.w = fmaxf(r1.w, 0.f);
        }
        *(float4*)Cp = r0;
        *((float4*)Cp + 1) = r1;
    }
}

// -------------------------------------------------------------- attention ----
// One block per sequence (8192). 16 keys/values at rows seq*16+j of Km/Vm.
// nq queries at rows seq*nq+i of Q. Each warp = one head.
__global__ void attn_kernel(const float* __restrict__ Q,
                            const float* __restrict__ Km,
                            const float* __restrict__ Vm,
                            float* __restrict__ O, int nq) {
    int seq = blockIdx.x;
    __shared__ float ks[DM * 17];       // transposed, padded: ks[c*17 + j]
    __shared__ float vs[KK * DM];       // row-major
    __shared__ float sc[NH][KK];
    int t = threadIdx.x;
    for (int i = t; i < KK * DM; i += 256) {
        int j = i >> 8;
        int c = i & 255;
        ks[c * 17 + j] = Km[(seq * KK + j) * DM + c];
        vs[j * DM + c] = Vm[(seq * KK + j) * DM + c];
    }
    __syncthreads();
    int h = t >> 5, lane = t & 31;
    for (int i = 0; i < nq; i++) {
        const float* q = Q + (seq * nq + i) * DM + h * DH;
        float s = -CUDART_INF_F;
        if (lane < KK) {
            float a = 0.f;
            #pragma unroll
            for (int e = 0; e < DH; e++) a += q[e] * ks[(h * DH + e) * 17 + lane];
            s = a * 0.17677669529663687f;  // 1/sqrt(32)
        }
        float m = s;
        #pragma unroll
        for (int o = 16; o > 0; o >>= 1) m = fmaxf(m, __shfl_xor_sync(0xffffffffu, m, o));
        float p = (lane < KK) ? expf(s - m) : 0.f;
        float sum = p;
        #pragma unroll
        for (int o = 16; o > 0; o >>= 1) sum += __shfl_xor_sync(0xffffffffu, sum, o);
        if (lane < KK) sc[h][lane] = p / sum;
        __syncwarp();
        float oa = 0.f;
        #pragma unroll
        for (int j = 0; j < KK; j++) oa += sc[h][j] * vs[j * DM + h * DH + lane];
        O[(seq * nq + i) * DM + h * DH + lane] = oa;
        __syncwarp();
    }
}

// ------------------------------------------------- final LN + generator ------
__global__ void final_kernel(const float* __restrict__ T,
                             const float* __restrict__ Wg,
                             float* __restrict__ out) {
    int seq = blockIdx.x;
    int t = threadIdx.x;
    __shared__ float y[DM];
    __shared__ float red[DM];
    float v = T[seq * DM + t];
    red[t] = v;
    __syncthreads();
    for (int s = 128; s > 0; s >>= 1) { if (t < s) red[t] += red[t + s]; __syncthreads(); }
    float mean = red[0] * (1.f / 256.f);
    __syncthreads();
    float d = v - mean;
    red[t] = d * d;
    __syncthreads();
    for (int s = 128; s > 0; s >>= 1) { if (t < s) red[t] += red[t + s]; __syncthreads(); }
    float r = rsqrtf(red[0] * (1.f / 256.f) + 1e-6f);
    y[t] = d * r;
    __syncthreads();
    if (t < SEQ) {
        float acc = 0.f;
        for (int dd = 0; dd < DM; dd++) acc += y[dd] * Wg[dd * SEQ + t];
        out[seq * SEQ + t] = acc;
    }
}

// ------------------------------------------------------------------ launch ---
extern "C" void kernel_launch(void* const* d_in, const int* in_sizes, int n_in,
                              void* d_out, int out_size) {
    const float* x_c      = (const float*)d_in[0];
    const float* A        = (const float*)d_in[1];
    const float* Wsrc     = (const float*)d_in[2];
    const float* Wtgt     = (const float*)d_in[3];
    const float* enc_attn = (const float*)d_in[4];
    const float* enc_ffn1 = (const float*)d_in[5];
    const float* enc_ffn2 = (const float*)d_in[6];
    const float* dec_self = (const float*)d_in[7];
    const float* dec_cross= (const float*)d_in[8];
    const float* dec_ffn1 = (const float*)d_in[9];
    const float* dec_ffn2 = (const float*)d_in[10];
    const float* Wgen     = (const float*)d_in[11];
    float* out = (float*)d_out;

    float *src, *y, *q, *k, *v, *ao, *h, *mem, *tgt, *ty, *tq, *to, *th, *wc;
    int* idxp;
    cudaGetSymbolAddress((void**)&src, g_src);
    cudaGetSymbolAddress((void**)&y,   g_y);
    cudaGetSymbolAddress((void**)&q,   g_q);
    cudaGetSymbolAddress((void**)&k,   g_k);
    cudaGetSymbolAddress((void**)&v,   g_v);
    cudaGetSymbolAddress((void**)&ao,  g_ao);
    cudaGetSymbolAddress((void**)&h,   g_h);
    cudaGetSymbolAddress((void**)&mem, g_mem);
    cudaGetSymbolAddress((void**)&tgt, g_tgt);
    cudaGetSymbolAddress((void**)&ty,  g_ty);
    cudaGetSymbolAddress((void**)&tq,  g_tq);
    cudaGetSymbolAddress((void**)&to,  g_to);
    cudaGetSymbolAddress((void**)&th,  g_th);
    cudaGetSymbolAddress((void**)&wc,  g_wc);
    cudaGetSymbolAddress((void**)&idxp, g_idx);

    const dim3 gBig256(2, ET / 128);       // M=131072, N=256
    const dim3 gBig256x3(2, ET / 128, 3);  // q,k,v batched over z
    const dim3 gBig256x2(2, ET / 128, 2);  // cross k,v batched over z
    const dim3 gBig1024(8, ET / 128);      // M=131072, N=1024
    const dim3 gSml256(2, NT / 128);       // M=8192,  N=256
    const dim3 gSml1024(8, NT / 128);      // M=8192,  N=1024
    const dim3 gWc(2, 2);                  // 256x256x256

    topk_kernel<<<NODES, 256>>>(A, idxp);
    embed_src_kernel<<<NT, 256>>>(x_c, idxp, Wsrc, src);
    embed_tgt_kernel<<<NT, 256>>>(x_c, Wtgt, tgt);

    // ------------------------------ encoder ------------------------------
    for (int l = 0; l < NL; l++) {
        const float* W = enc_attn + (long)l * 4 * DD;
        ln_kernel<<<ET / 8, 256>>>(src, y, ET);
        // q,k,v in one launch: z strides B by DD and C by ET*DM (q,k,v contiguous)
        sgemm<0><<<gBig256x3, 256>>>(y, W, q, ET, DM, DM, 0, DD, (long)ET * DM);
        attn_kernel<<<NT, 256>>>(q, k, v, ao, KK);
        sgemm<1><<<gBig256, 256>>>(ao, W + 3 * DD, src, ET, DM, DM, 0, 0, 0);
        ln_kernel<<<ET / 8, 256>>>(src, y, ET);
        sgemm<2><<<gBig1024, 256>>>(y, enc_ffn1 + (long)l * DM * DFF, h, ET, DFF, DM, 0, 0, 0);
        sgemm<1><<<gBig256, 256>>>(h, enc_ffn2 + (long)l * DFF * DM, src, ET, DM, DFF, 0, 0, 0);
    }
    ln_kernel<<<ET / 8, 256>>>(src, mem, ET);

    // ------------------------------ decoder ------------------------------
    for (int l = 0; l < NL; l++) {
        const float* Wd = dec_self  + (long)l * 4 * DD;
        const float* Wx = dec_cross + (long)l * 4 * DD;
        // self-attn over 1 token: softmax==1 exactly -> tgt += ln(tgt) @ (W2@W3)
        ln_kernel<<<NT / 8, 256>>>(tgt, ty, NT);
        sgemm<0><<<gWc, 256>>>(Wd + 2 * DD, Wd + 3 * DD, wc, DM, DM, DM, 0, 0, 0);
        sgemm<1><<<gSml256, 256>>>(ty, wc, tgt, NT, DM, DM, 0, 0, 0);
        // cross-attn
        ln_kernel<<<NT / 8, 256>>>(tgt, ty, NT);
        sgemm<0><<<gSml256, 256>>>(ty, Wx + 0 * DD, tq, NT, DM, DM, 0, 0, 0);
        // k,v over memory in one launch (g_k, g_v contiguous)
        sgemm<0><<<gBig256x2, 256>>>(mem, Wx + 1 * DD, k, ET, DM, DM, 0, DD, (long)ET * DM);
        attn_kernel<<<NT, 256>>>(tq, k, v, to, 1);
        sgemm<1><<<gSml256, 256>>>(to, Wx + 3 * DD, tgt, NT, DM, DM, 0, 0, 0);
        // ffn
        ln_kernel<<<NT / 8, 256>>>(tgt, ty, NT);
        sgemm<2><<<gSml1024, 256>>>(ty, dec_ffn1 + (long)l * DM * DFF, th, NT, DFF, DM, 0, 0, 0);
        sgemm<1><<<gSml256, 256>>>(th, dec_ffn2 + (long)l * DFF * DM, tgt, NT, DM, DFF, 0, 0, 0);
    }

    final_kernel<<<NT, 256>>>(tgt, Wgen, out);
}

// round 8
// speedup vs baseline: 2.1230x; 2.1230x over previous
#include <cuda_runtime.h>
#include <cuda_bf16.h>
#include <cstdint>
#include <math.h>
#include <math_constants.h>

#define BSZ      16
#define SEQ      12
#define NODES    512
#define DM       256
#define NH       8
#define DH       32
#define NL       2
#define KK       16
#define DFF      1024
#define NT       (BSZ * NODES)        // 8192 decoder tokens / sequences
#define ET       (NT * KK)            // 131072 encoder tokens
#define DD       (DM * DM)            // 65536

typedef __nv_bfloat16 bf16;

// ------------------------- scratch (device globals; no cudaMalloc allowed) ---
__device__ float g_src[ET * DM];
__device__ float g_qkv[3L * ET * DM];          // q | k | v contiguous
__device__ float g_tgt[NT * DM];
__device__ float g_tq [NT * DM];
__device__ float g_wc [DM * DM];
__device__ int   g_idx[NODES * KK];

__device__ bf16 g_yh [ET * DM];  __device__ bf16 g_yl [ET * DM];
__device__ bf16 g_aoh[ET * DM];  __device__ bf16 g_aol[ET * DM];
__device__ bf16 g_hh [ET * DFF]; __device__ bf16 g_hl [ET * DFF];
__device__ bf16 g_mh [ET * DM];  __device__ bf16 g_ml [ET * DM];
__device__ bf16 g_tyh[NT * DM];  __device__ bf16 g_tyl[NT * DM];
__device__ bf16 g_toh[NT * DM];  __device__ bf16 g_tol[NT * DM];
__device__ bf16 g_thh[NT * DFF]; __device__ bf16 g_thl[NT * DFF];
// transposed weights, hi/lo
__device__ bf16 g_weh [8 * DD];        __device__ bf16 g_wel [8 * DD];
__device__ bf16 g_wf1h[2 * DM * DFF];  __device__ bf16 g_wf1l[2 * DM * DFF];
__device__ bf16 g_wf2h[2 * DFF * DM];  __device__ bf16 g_wf2l[2 * DFF * DM];
__device__ bf16 g_wxh [8 * DD];        __device__ bf16 g_wxl [8 * DD];
__device__ bf16 g_wg1h[2 * DM * DFF];  __device__ bf16 g_wg1l[2 * DM * DFF];
__device__ bf16 g_wg2h[2 * DFF * DM];  __device__ bf16 g_wg2l[2 * DFF * DM];
__device__ bf16 g_wch [DD];            __device__ bf16 g_wcl [DD];

// ------------------------------------------------------------- helpers -------
__device__ __forceinline__ uint32_t smem_u32(const void* p) {
    uint32_t a;
    asm("{ .reg .u64 t; cvta.to.shared.u64 t, %1; cvt.u32.u64 %0, t; }" : "=r"(a) : "l"(p));
    return a;
}
__device__ __forceinline__ void split_bf16(float f, bf16& h, bf16& l) {
    h = __float2bfloat16_rn(f);
    l = __float2bfloat16_rn(f - __bfloat162float(h));
}
__device__ __forceinline__ void cp16(uint32_t dst, const void* src) {
    asm volatile("cp.async.ca.shared.global [%0], [%1], 16;" :: "r"(dst), "l"(src) : "memory");
}
__device__ __forceinline__ void ldsm4(uint32_t* r, uint32_t addr) {
    asm volatile("ldmatrix.sync.aligned.m8n8.x4.shared.b16 {%0,%1,%2,%3}, [%4];"
        : "=r"(r[0]), "=r"(r[1]), "=r"(r[2]), "=r"(r[3]) : "r"(addr));
}
__device__ __forceinline__ void mma16816(float* c, const uint32_t* a,
                                         uint32_t b0, uint32_t b1) {
    asm volatile("mma.sync.aligned.m16n8k16.row.col.f32.bf16.bf16.f32 "
        "{%0,%1,%2,%3}, {%4,%5,%6,%7}, {%8,%9}, {%0,%1,%2,%3};"
        : "+f"(c[0]), "+f"(c[1]), "+f"(c[2]), "+f"(c[3])
        : "r"(a[0]), "r"(a[1]), "r"(a[2]), "r"(a[3]), "r"(b0), "r"(b1));
}

// ------------------------------------------------------------------ top-K ----
__global__ void topk_kernel(const float* __restrict__ A, int* __restrict__ idx) {
    int n = blockIdx.x;
    __shared__ float sv[512];
    __shared__ float rv[256];
    __shared__ int   ri[256];
    int t = threadIdx.x;
    sv[t]       = A[n * 512 + t];
    sv[t + 256] = A[n * 512 + t + 256];
    __syncthreads();
    for (int it = 0; it < KK; it++) {
        float best = sv[t]; int bi = t;
        float v2 = sv[t + 256];
        if (v2 > best) { best = v2; bi = t + 256; }
        rv[t] = best; ri[t] = bi;
        __syncthreads();
        for (int s = 128; s > 0; s >>= 1) {
            if (t < s) {
                if (rv[t + s] > rv[t] || (rv[t + s] == rv[t] && ri[t + s] < ri[t])) {
                    rv[t] = rv[t + s]; ri[t] = ri[t + s];
                }
            }
            __syncthreads();
        }
        if (t == 0) { idx[n * KK + it] = ri[0]; sv[ri[0]] = -CUDART_INF_F; }
        __syncthreads();
    }
}

// ------------------------------------------------------ positional encoding --
__device__ __forceinline__ float pe_val(int p, int d) {
    int i2 = d & ~1;
    float div = expf(-(float)i2 * (9.210340371976184f / 256.f));
    float ang = (float)p * div;
    return (d & 1) ? cosf(ang) : sinf(ang);
}

// -------------------------------------------------------------- embeddings ---
__global__ void embed_src_kernel(const float* __restrict__ xc,
                                 const int* __restrict__ idx,
                                 const float* __restrict__ Wsrc,
                                 float* __restrict__ src) {
    int seq = blockIdx.x;
    int b = seq >> 9, n = seq & 511;
    __shared__ float Ws[SEQ * DM];
    __shared__ float xv[KK * SEQ];
    int t = threadIdx.x;
    for (int i = t; i < SEQ * DM; i += 256) Ws[i] = Wsrc[i];
    if (t < KK * SEQ) {
        int j = t / SEQ, s = t % SEQ;
        int node = idx[n * KK + j];
        xv[t] = xc[(b * SEQ + s) * NODES + node];
    }
    __syncthreads();
    for (int j = 0; j < KK; j++) {
        float acc = 0.f;
        #pragma unroll
        for (int s = 0; s < SEQ; s++) acc += xv[j * SEQ + s] * Ws[s * DM + t];
        src[(seq * KK + j) * DM + t] = acc * 16.f + pe_val(j, t);
    }
}

__global__ void embed_tgt_kernel(const float* __restrict__ xc,
                                 const float* __restrict__ Wtgt,
                                 float* __restrict__ tgt) {
    int seq = blockIdx.x;
    int b = seq >> 9, n = seq & 511;
    __shared__ float xv[SEQ];
    int t = threadIdx.x;
    if (t < SEQ) xv[t] = xc[(b * SEQ + t) * NODES + n];
    __syncthreads();
    float acc = 0.f;
    #pragma unroll
    for (int s = 0; s < SEQ; s++) acc += xv[s] * Wtgt[s * DM + t];
    tgt[seq * DM + t] = acc * 16.f + ((t & 1) ? 1.f : 0.f);
}

// ---------------------------------------------------- layernorm -> hi/lo -----
__global__ void ln_kernel(const float* __restrict__ X, bf16* __restrict__ Yh,
                          bf16* __restrict__ Yl, int rows) {
    int row = blockIdx.x * 8 + (threadIdx.x >> 5);
    if (row >= rows) return;
    int lane = threadIdx.x & 31;
    const float* x = X + (long)row * DM;
    float vals[8];
    float s = 0.f;
    #pragma unroll
    for (int i = 0; i < 8; i++) { vals[i] = x[lane + i * 32]; s += vals[i]; }
    #pragma unroll
    for (int o = 16; o > 0; o >>= 1) s += __shfl_xor_sync(0xffffffffu, s, o);
    float mean = s * (1.f / 256.f);
    float s2 = 0.f;
    #pragma unroll
    for (int i = 0; i < 8; i++) { float d = vals[i] - mean; s2 += d * d; }
    #pragma unroll
    for (int o = 16; o > 0; o >>= 1) s2 += __shfl_xor_sync(0xffffffffu, s2, o);
    float r = rsqrtf(s2 * (1.f / 256.f) + 1e-6f);
    bf16* yh = Yh + (long)row * DM;
    bf16* yl = Yl + (long)row * DM;
    #pragma unroll
    for (int i = 0; i < 8; i++) {
        bf16 h, l; split_bf16((vals[i] - mean) * r, h, l);
        yh[lane + i * 32] = h;
        yl[lane + i * 32] = l;
    }
}

// ---------------------------------------- weight convert + transpose ---------
// W [K,N] fp32 -> Th/Tl [N,K] bf16 (hi/lo). z batches matrices.
__global__ void convw(const float* __restrict__ W, bf16* __restrict__ Th,
                      bf16* __restrict__ Tl, int K, int N, long sW, long sT) {
    long z = blockIdx.z;
    int idx = blockIdx.x * 256 + threadIdx.x;
    float f = W[z * sW + idx];
    int k = idx / N, n = idx - k * N;
    bf16 h, l; split_bf16(f, h, l);
    Th[z * sT + (long)n * K + k] = h;
    Tl[z * sT + (long)n * K + k] = l;
}

// ------------------------------------- HMMA tensor-core GEMM (bf16 hi/lo) ----
// C[M,N] (op)= A[M,K] @ Bt[N,K]^T, fp32 accum, 3 bf16 mma passes.
// CTA tile 128x128, warp tile 64x32 (8 warps), k-chunk 32, cp.async 2-stage.
// EPI: 0 = store fp32, 1 = C += fp32, 2 = relu -> hi/lo bf16.
#define TGS     80                         // smem bytes per row (32 bf16 + 8 pad)
#define TGT     (128 * TGS)                // 10240 per tile
#define TGSTAGE (4 * TGT)                  // Ah|Al|Bh|Bl = 40960
#define TG_SMEM (2 * TGSTAGE)              // 81920

template<int EPI>
__global__ void __launch_bounds__(256, 2) tgemm(
    const bf16* __restrict__ Ah, const bf16* __restrict__ Al,
    const bf16* __restrict__ Bh, const bf16* __restrict__ Bl,
    float* __restrict__ Cf, bf16* __restrict__ Ch, bf16* __restrict__ Cl,
    int N, int K, long strideB, long strideC)
{
    extern __shared__ char smem[];
    const int bn = blockIdx.x, bm = blockIdx.y, bz = blockIdx.z;
    const uint32_t sb = smem_u32(smem);
    int t = threadIdx.x;
    int wid = t >> 5, lane = t & 31;
    int wm = wid & 1, wn = wid >> 1;          // 2 x 4 warp grid

    const bf16* gsrc[4];
    gsrc[0] = Ah + (long)bm * 128 * K;
    gsrc[1] = Al + (long)bm * 128 * K;
    gsrc[2] = Bh + (long)bz * strideB + (long)bn * 128 * K;
    gsrc[3] = Bl + (long)bz * strideB + (long)bn * 128 * K;

    float acc[4][4][4];
    #pragma unroll
    for (int i = 0; i < 4; i++)
        #pragma unroll
        for (int j = 0; j < 4; j++)
            #pragma unroll
            for (int r = 0; r < 4; r++) acc[i][j][r] = 0.f;

    const int nch = K >> 5;

    // --- async chunk loader: 8 x 16B per thread ---
    auto load_chunk = [&](int c, int buf) {
        int k0 = c << 5;
        uint32_t sbase = sb + buf * TGSTAGE;
        #pragma unroll
        for (int i = 0; i < 8; i++) {
            int id = i * 256 + t;
            int tile = id >> 9, rem = id & 511;
            int row = rem >> 2, seg = rem & 3;
            uint32_t dst = sbase + tile * TGT + row * TGS + seg * 16;
            const char* src = (const char*)(gsrc[tile] + (long)row * K + k0) + seg * 16;
            cp16(dst, src);
        }
        asm volatile("cp.async.commit_group;" ::: "memory");
    };

    load_chunk(0, 0);

    for (int c = 0; c < nch; c++) {
        if (c + 1 < nch) {
            load_chunk(c + 1, (c + 1) & 1);
            asm volatile("cp.async.wait_group 1;" ::: "memory");
        } else {
            asm volatile("cp.async.wait_group 0;" ::: "memory");
        }
        __syncthreads();

        uint32_t st = sb + (c & 1) * TGSTAGE;
        uint32_t aHi = st + 0 * TGT, aLo = st + 1 * TGT;
        uint32_t bHi = st + 2 * TGT, bLo = st + 3 * TGT;

        #pragma unroll
        for (int h = 0; h < 2; h++) {
            // lane address patterns
            int arow = lane & 15, asel = lane >> 4;                 // A matrices
            int brow = (lane & 7) + ((lane >> 4) << 3);             // B matrices
            int bsel = (lane >> 3) & 1;

            uint32_t af[4][4], bfm[2][4];
            // ---- pass 0: Ah * Bh ----
            #pragma unroll
            for (int mt = 0; mt < 4; mt++)
                ldsm4(af[mt], aHi + (wm * 64 + mt * 16 + arow) * TGS + h * 32 + asel * 16);
            #pragma unroll
            for (int bt = 0; bt < 2; bt++)
                ldsm4(bfm[bt], bHi + (wn * 32 + bt * 16 + brow) * TGS + h * 32 + bsel * 16);
            #pragma unroll
            for (int mt = 0; mt < 4; mt++)
                #pragma unroll
                for (int na = 0; na < 4; na++)
                    mma16816(acc[mt][na], af[mt], bfm[na >> 1][(na & 1) * 2],
                             bfm[na >> 1][(na & 1) * 2 + 1]);
            // ---- pass 1: Ah * Bl ----
            uint32_t bfl[2][4];
            #pragma unroll
            for (int bt = 0; bt < 2; bt++)
                ldsm4(bfl[bt], bLo + (wn * 32 + bt * 16 + brow) * TGS + h * 32 + bsel * 16);
            #pragma unroll
            for (int mt = 0; mt < 4; mt++)
                #pragma unroll
                for (int na = 0; na < 4; na++)
                    mma16816(acc[mt][na], af[mt], bfl[na >> 1][(na & 1) * 2],
                             bfl[na >> 1][(na & 1) * 2 + 1]);
            // ---- pass 2: Al * Bh ----
            #pragma unroll
            for (int mt = 0; mt < 4; mt++)
                ldsm4(af[mt], aLo + (wm * 64 + mt * 16 + arow) * TGS + h * 32 + asel * 16);
            #pragma unroll
            for (int mt = 0; mt < 4; mt++)
                #pragma unroll
                for (int na = 0; na < 4; na++)
                    mma16816(acc[mt][na], af[mt], bfm[na >> 1][(na & 1) * 2],
                             bfm[na >> 1][(na & 1) * 2 + 1]);
        }
        __syncthreads();
    }

    // ------------------------------- epilogue -------------------------------
    int r = lane >> 2, c2 = (lane & 3) * 2;
    #pragma unroll
    for (int mt = 0; mt < 4; mt++) {
        int m0 = bm * 128 + wm * 64 + mt * 16;
        #pragma unroll
        for (int na = 0; na < 4; na++) {
            int n0 = bn * 128 + wn * 32 + na * 8 + c2;
            long i0 = (long)bz * strideC + (long)(m0 + r) * N + n0;
            long i1 = (long)bz * strideC + (long)(m0 + r + 8) * N + n0;
            float* a = acc[mt][na];
            if (EPI == 0) {
                *(float2*)(Cf + i0) = make_float2(a[0], a[1]);
                *(float2*)(Cf + i1) = make_float2(a[2], a[3]);
            } else if (EPI == 1) {
                float2 v0 = *(float2*)(Cf + i0);
                float2 v1 = *(float2*)(Cf + i1);
                v0.x += a[0]; v0.y += a[1]; v1.x += a[2]; v1.y += a[3];
                *(float2*)(Cf + i0) = v0;
                *(float2*)(Cf + i1) = v1;
            } else {
                float f0 = fmaxf(a[0], 0.f), f1 = fmaxf(a[1], 0.f);
                float f2 = fmaxf(a[2], 0.f), f3 = fmaxf(a[3], 0.f);
                bf16 h0, l0, h1, l1, h2, l2, h3, l3;
                split_bf16(f0, h0, l0); split_bf16(f1, h1, l1);
                split_bf16(f2, h2, l2); split_bf16(f3, h3, l3);
                *(__nv_bfloat162*)(Ch + i0) = __halves2bfloat162(h0, h1);
                *(__nv_bfloat162*)(Cl + i0) = __halves2bfloat162(l0, l1);
                *(__nv_bfloat162*)(Ch + i1) = __halves2bfloat162(h2, h3);
                *(__nv_bfloat162*)(Cl + i1) = __halves2bfloat162(l2, l3);
            }
        }
    }
}

// ------------------------------------------ fp32 GEMM (only for wc, 256^3) ---
__global__ void __launch_bounds__(256) sgemm0(const float* __restrict__ A,
                                              const float* __restrict__ B,
                                              float* __restrict__ C,
                                              int M, int N, int K) {
    const int bm = blockIdx.y, bn = blockIdx.x;
    __shared__ float As[2][8][128];
    __shared__ float Bs[2][8][128];
    int t = threadIdx.x;
    int tx = t & 15, ty = t >> 4;
    int arow = t >> 1, acol = (t & 1) * 4;
    int brow = t >> 5, bcol = (t & 31) * 4;
    const float* Ag = A + (bm * 128 + arow) * K + acol;
    const float* Bg = B + brow * N + bn * 128 + bcol;
    float acc[8][8];
    #pragma unroll
    for (int i = 0; i < 8; i++)
        #pragma unroll
        for (int j = 0; j < 8; j++) acc[i][j] = 0.f;
    float4 a4 = *(const float4*)Ag;
    float4 b4 = *(const float4*)Bg;
    As[0][acol + 0][arow] = a4.x; As[0][acol + 1][arow] = a4.y;
    As[0][acol + 2][arow] = a4.z; As[0][acol + 3][arow] = a4.w;
    *(float4*)&Bs[0][brow][bcol] = b4;
    __syncthreads();
    int nk = K >> 3;
    for (int kt = 0; kt < nk; kt++) {
        int cur = kt & 1;
        if (kt + 1 < nk) {
            a4 = *(const float4*)(Ag + (kt + 1) * 8);
            b4 = *(const float4*)(Bg + (kt + 1) * 8 * N);
        }
        #pragma unroll
        for (int kk = 0; kk < 8; kk++) {
            float ar[8], br[8];
            *(float4*)(ar)     = *(const float4*)&As[cur][kk][ty * 8];
            *(float4*)(ar + 4) = *(const float4*)&As[cur][kk][ty * 8 + 4];
            *(float4*)(br)     = *(const float4*)&Bs[cur][kk][tx * 8];
            *(float4*)(br + 4) = *(const float4*)&Bs[cur][kk][tx * 8 + 4];
            #pragma unroll
            for (int i = 0; i < 8; i++)
                #pragma unroll
                for (int j = 0; j < 8; j++) acc[i][j] += ar[i] * br[j];
        }
        if (kt + 1 < nk) {
            int nxt = cur ^ 1;
            As[nxt][acol + 0][arow] = a4.x; As[nxt][acol + 1][arow] = a4.y;
            As[nxt][acol + 2][arow] = a4.z; As[nxt][acol + 3][arow] = a4.w;
            *(float4*)&Bs[nxt][brow][bcol] = b4;
            __syncthreads();
        }
    }
    #pragma unroll
    for (int i = 0; i < 8; i++) {
        float* Cp = C + (bm * 128 + ty * 8 + i) * N + bn * 128 + tx * 8;
        *(float4*)Cp       = make_float4(acc[i][0], acc[i][1], acc[i][2], acc[i][3]);
        *((float4*)Cp + 1) = make_float4(acc[i][4], acc[i][5], acc[i][6], acc[i][7]);
    }
}

// -------------------------------------------------------------- attention ----
__global__ void attn_kernel(const float* __restrict__ Q,
                            const float* __restrict__ Km,
                            const float* __restrict__ Vm,
                            bf16* __restrict__ Oh, bf16* __restrict__ Ol, int nq) {
    int seq = blockIdx.x;
    __shared__ float ks[DM * 17];
    __shared__ float vs[KK * DM];
    __shared__ float sc[NH][KK];
    int t = threadIdx.x;
    for (int i = t; i < KK * DM; i += 256) {
        int j = i >> 8;
        int c = i & 255;
        ks[c * 17 + j] = Km[(seq * KK + j) * DM + c];
        vs[j * DM + c] = Vm[(seq * KK + j) * DM + c];
    }
    __syncthreads();
    int h = t >> 5, lane = t & 31;
    for (int i = 0; i < nq; i++) {
        const float* q = Q + (long)(seq * nq + i) * DM + h * DH;
        float s = -CUDART_INF_F;
        if (lane < KK) {
            float a = 0.f;
            #pragma unroll
            for (int e = 0; e < DH; e++) a += q[e] * ks[(h * DH + e) * 17 + lane];
            s = a * 0.17677669529663687f;
        }
        float m = s;
        #pragma unroll
        for (int o = 16; o > 0; o >>= 1) m = fmaxf(m, __shfl_xor_sync(0xffffffffu, m, o));
        float p = (lane < KK) ? expf(s - m) : 0.f;
        float sum = p;
        #pragma unroll
        for (int o = 16; o > 0; o >>= 1) sum += __shfl_xor_sync(0xffffffffu, sum, o);
        if (lane < KK) sc[h][lane] = p / sum;
        __syncwarp();
        float oa = 0.f;
        #pragma unroll
        for (int j = 0; j < KK; j++) oa += sc[h][j] * vs[j * DM + h * DH + lane];
        bf16 hh, ll; split_bf16(oa, hh, ll);
        long oi = (long)(seq * nq + i) * DM + h * DH + lane;
        Oh[oi] = hh;
        Ol[oi] = ll;
        __syncwarp();
    }
}

// ------------------------------------------------- final LN + generator ------
__global__ void final_kernel(const float* __restrict__ T,
                             const float* __restrict__ Wg,
                             float* __restrict__ out) {
    int seq = blockIdx.x;
    int t = threadIdx.x;
    __shared__ float y[DM];
    __shared__ float red[DM];
    float v = T[seq * DM + t];
    red[t] = v;
    __syncthreads();
    for (int s = 128; s > 0; s >>= 1) { if (t < s) red[t] += red[t + s]; __syncthreads(); }
    float mean = red[0] * (1.f / 256.f);
    __syncthreads();
    float d = v - mean;
    red[t] = d * d;
    __syncthreads();
    for (int s = 128; s > 0; s >>= 1) { if (t < s) red[t] += red[t + s]; __syncthreads(); }
    float r = rsqrtf(red[0] * (1.f / 256.f) + 1e-6f);
    y[t] = d * r;
    __syncthreads();
    if (t < SEQ) {
        float acc = 0.f;
        for (int dd = 0; dd < DM; dd++) acc += y[dd] * Wg[dd * SEQ + t];
        out[seq * SEQ + t] = acc;
    }
}

// ------------------------------------------------------------------ launch ---
extern "C" void kernel_launch(void* const* d_in, const int* in_sizes, int n_in,
                              void* d_out, int out_size) {
    const float* x_c      = (const float*)d_in[0];
    const float* A        = (const float*)d_in[1];
    const float* Wsrc     = (const float*)d_in[2];
    const float* Wtgt     = (const float*)d_in[3];
    const float* enc_attn = (const float*)d_in[4];
    const float* enc_ffn1 = (const float*)d_in[5];
    const float* enc_ffn2 = (const float*)d_in[6];
    const float* dec_self = (const float*)d_in[7];
    const float* dec_cross= (const float*)d_in[8];
    const float* dec_ffn1 = (const float*)d_in[9];
    const float* dec_ffn2 = (const float*)d_in[10];
    const float* Wgen     = (const float*)d_in[11];
    float* out = (float*)d_out;

    cudaFuncSetAttribute(tgemm<0>, cudaFuncAttributeMaxDynamicSharedMemorySize, TG_SMEM);
    cudaFuncSetAttribute(tgemm<1>, cudaFuncAttributeMaxDynamicSharedMemorySize, TG_SMEM);
    cudaFuncSetAttribute(tgemm<2>, cudaFuncAttributeMaxDynamicSharedMemorySize, TG_SMEM);

    float *src, *qkv, *tgt, *tq, *wc;  int* idxp;
    cudaGetSymbolAddress((void**)&src, g_src);
    cudaGetSymbolAddress((void**)&qkv, g_qkv);
    cudaGetSymbolAddress((void**)&tgt, g_tgt);
    cudaGetSymbolAddress((void**)&tq,  g_tq);
    cudaGetSymbolAddress((void**)&wc,  g_wc);
    cudaGetSymbolAddress((void**)&idxp, g_idx);
    bf16 *yh,*yl,*aoh,*aol,*hh,*hl,*mh,*ml,*tyh,*tyl,*toh,*tol,*thh,*thl;
    bf16 *weh,*wel,*wf1h,*wf1l,*wf2h,*wf2l,*wxh,*wxl,*wg1h,*wg1l,*wg2h,*wg2l,*wch,*wcl;
    cudaGetSymbolAddress((void**)&yh, g_yh);   cudaGetSymbolAddress((void**)&yl, g_yl);
    cudaGetSymbolAddress((void**)&aoh, g_aoh); cudaGetSymbolAddress((void**)&aol, g_aol);
    cudaGetSymbolAddress((void**)&hh, g_hh);   cudaGetSymbolAddress((void**)&hl, g_hl);
    cudaGetSymbolAddress((void**)&mh, g_mh);   cudaGetSymbolAddress((void**)&ml, g_ml);
    cudaGetSymbolAddress((void**)&tyh, g_tyh); cudaGetSymbolAddress((void**)&tyl, g_tyl);
    cudaGetSymbolAddress((void**)&toh, g_toh); cudaGetSymbolAddress((void**)&tol, g_tol);
    cudaGetSymbolAddress((void**)&thh, g_thh); cudaGetSymbolAddress((void**)&thl, g_thl);
    cudaGetSymbolAddress((void**)&weh, g_weh);   cudaGetSymbolAddress((void**)&wel, g_wel);
    cudaGetSymbolAddress((void**)&wf1h, g_wf1h); cudaGetSymbolAddress((void**)&wf1l, g_wf1l);
    cudaGetSymbolAddress((void**)&wf2h, g_wf2h); cudaGetSymbolAddress((void**)&wf2l, g_wf2l);
    cudaGetSymbolAddress((void**)&wxh, g_wxh);   cudaGetSymbolAddress((void**)&wxl, g_wxl);
    cudaGetSymbolAddress((void**)&wg1h, g_wg1h); cudaGetSymbolAddress((void**)&wg1l, g_wg1l);
    cudaGetSymbolAddress((void**)&wg2h, g_wg2h); cudaGetSymbolAddress((void**)&wg2l, g_wg2l);
    cudaGetSymbolAddress((void**)&wch, g_wch);   cudaGetSymbolAddress((void**)&wcl, g_wcl);

    float* q = qkv;
    float* k = qkv + (long)ET * DM;
    float* v = qkv + 2L * ET * DM;

    // ---- weight conversion (transposed, hi/lo) ----
    convw<<<dim3(DD / 256, 1, 8), 256>>>(enc_attn, weh, wel, DM, DM, DD, DD);
    convw<<<dim3(DM * DFF / 256, 1, 2), 256>>>(enc_ffn1, wf1h, wf1l, DM, DFF, (long)DM * DFF, (long)DM * DFF);
    convw<<<dim3(DM * DFF / 256, 1, 2), 256>>>(enc_ffn2, wf2h, wf2l, DFF, DM, (long)DM * DFF, (long)DM * DFF);
    convw<<<dim3(DD / 256, 1, 8), 256>>>(dec_cross, wxh, wxl, DM, DM, DD, DD);
    convw<<<dim3(DM * DFF / 256, 1, 2), 256>>>(dec_ffn1, wg1h, wg1l, DM, DFF, (long)DM * DFF, (long)DM * DFF);
    convw<<<dim3(DM * DFF / 256, 1, 2), 256>>>(dec_ffn2, wg2h, wg2l, DFF, DM, (long)DM * DFF, (long)DM * DFF);

    topk_kernel<<<NODES, 256>>>(A, idxp);
    embed_src_kernel<<<NT, 256>>>(x_c, idxp, Wsrc, src);
    embed_tgt_kernel<<<NT, 256>>>(x_c, Wtgt, tgt);

    const dim3 gB2(2, ET / 128, 1), gB2x3(2, ET / 128, 3), gB2x2(2, ET / 128, 2), gB8(8, ET / 128, 1);
    const dim3 gS2(2, NT / 128, 1), gS8(8, NT / 128, 1);

    // ------------------------------ encoder ------------------------------
    for (int l = 0; l < NL; l++) {
        long wo = (long)l * 4 * DD;
        ln_kernel<<<ET / 8, 256>>>(src, yh, yl, ET);
        tgemm<0><<<gB2x3, 256, TG_SMEM>>>(yh, yl, weh + wo, wel + wo, q, 0, 0,
                                          DM, DM, DD, (long)ET * DM);
        attn_kernel<<<NT, 256>>>(q, k, v, aoh, aol, KK);
        tgemm<1><<<gB2, 256, TG_SMEM>>>(aoh, aol, weh + wo + 3 * DD, wel + wo + 3 * DD,
                                        src, 0, 0, DM, DM, 0, 0);
        ln_kernel<<<ET / 8, 256>>>(src, yh, yl, ET);
        long f1 = (long)l * DM * DFF;
        tgemm<2><<<gB8, 256, TG_SMEM>>>(yh, yl, wf1h + f1, wf1l + f1, 0, hh, hl,
                                        DFF, DM, 0, 0);
        tgemm<1><<<gB2, 256, TG_SMEM>>>(hh, hl, wf2h + f1, wf2l + f1, src, 0, 0,
                                        DM, DFF, 0, 0);
    }
    ln_kernel<<<ET / 8, 256>>>(src, mh, ml, ET);

    // ------------------------------ decoder ------------------------------
    for (int l = 0; l < NL; l++) {
        const float* Wd = dec_self + (long)l * 4 * DD;
        long wo = (long)l * 4 * DD;
        long f1 = (long)l * DM * DFF;
        // self-attn over 1 token == identity softmax -> tgt += ln(tgt) @ (W2@W3)
        ln_kernel<<<NT / 8, 256>>>(tgt, tyh, tyl, NT);
        sgemm0<<<dim3(2, 2), 256>>>(Wd + 2 * DD, Wd + 3 * DD, wc, DM, DM, DM);
        convw<<<dim3(DD / 256, 1, 1), 256>>>(wc, wch, wcl, DM, DM, 0, 0);
        tgemm<1><<<gS2, 256, TG_SMEM>>>(tyh, tyl, wch, wcl, tgt, 0, 0, DM, DM, 0, 0);
        // cross-attn
        ln_kernel<<<NT / 8, 256>>>(tgt, tyh, tyl, NT);
        tgemm<0><<<gS2, 256, TG_SMEM>>>(tyh, tyl, wxh + wo, wxl + wo, tq, 0, 0, DM, DM, 0, 0);
        tgemm<0><<<gB2x2, 256, TG_SMEM>>>(mh, ml, wxh + wo + DD, wxl + wo + DD, k, 0, 0,
                                          DM, DM, DD, (long)ET * DM);
        attn_kernel<<<NT, 256>>>(tq, k, v, toh, tol, 1);
        tgemm<1><<<gS2, 256, TG_SMEM>>>(toh, tol, wxh + wo + 3 * DD, wxl + wo + 3 * DD,
                                        tgt, 0, 0, DM, DM, 0, 0);
        // ffn
        ln_kernel<<<NT / 8, 256>>>(tgt, tyh, tyl, NT);
        tgemm<2><<<gS8, 256, TG_SMEM>>>(tyh, tyl, wg1h + f1, wg1l + f1, 0, thh, thl,
                                        DFF, DM, 0, 0);
        tgemm<1><<<gS2, 256, TG_SMEM>>>(thh, thl, wg2h + f1, wg2l + f1, tgt, 0, 0,
                                        DM, DFF, 0, 0);
    }

    final_kernel<<<NT, 256>>>(tgt, Wgen, out);
}